// round 12
// baseline (speedup 1.0000x reference)
#include <cuda_runtime.h>
#include <cuda_bf16.h>
#include <cuda_fp16.h>
#include <math_constants.h>
#include <cstdint>

#define NSEQ 4096
#define DIN  1024
#define HID  512

typedef unsigned short u16;

// ---------------------------------------------------------------------------
// Device scratch
// ---------------------------------------------------------------------------
__device__ float g_S [(size_t)NSEQ * NSEQ];                // 64 MB logits
__device__ float g_rowInv[NSEQ];                           // 1/Z per row

__device__ __nv_bfloat16 g_ea [(size_t)NSEQ * 3 * DIN];    // embs bf16 a3-form
__device__ __nv_bfloat16 g_Wqb[(size_t)HID  * 3 * DIN];    // Wq  bf16 b3-form
__device__ __nv_bfloat16 g_Wkb[(size_t)HID  * 3 * DIN];    // Wk  bf16 b3-form
__device__ u16 g_eh [(size_t)NSEQ * DIN];                  // embs fp16
__device__ u16 g_Wvh[(size_t)HID  * DIN];                  // Wv   fp16
__device__ u16 g_Qa [(size_t)NSEQ * 2 * HID];              // [Qh | Ql] fp16
__device__ u16 g_Kb [(size_t)NSEQ * 2 * HID];              // [Kh | Kh] fp16
__device__ u16 g_Ph [(size_t)NSEQ * NSEQ];                 // exp(s-m) fp16, 32 MB
__device__ u16 g_Vth[(size_t)HID  * NSEQ];                 // Vt fp16

// ---------------------------------------------------------------------------
// Merged input conversions (one launch).
// ---------------------------------------------------------------------------
#define E4  (NSEQ * DIN / 4)            // 1048576
#define W4  (HID * DIN / 4)             // 131072

__device__ __forceinline__ void split3_store(
    float4 v, __nv_bfloat16* Y, int row, int col, int K, int bside)
{
    __nv_bfloat16 h0 = __float2bfloat16_rn(v.x);
    __nv_bfloat16 h1 = __float2bfloat16_rn(v.y);
    __nv_bfloat16 h2 = __float2bfloat16_rn(v.z);
    __nv_bfloat16 h3 = __float2bfloat16_rn(v.w);
    __nv_bfloat16 l0 = __float2bfloat16_rn(v.x - __bfloat162float(h0));
    __nv_bfloat16 l1 = __float2bfloat16_rn(v.y - __bfloat162float(h1));
    __nv_bfloat16 l2 = __float2bfloat16_rn(v.z - __bfloat162float(h2));
    __nv_bfloat16 l3 = __float2bfloat16_rn(v.w - __bfloat162float(h3));
    ushort4 ph = make_ushort4(__bfloat16_as_ushort(h0), __bfloat16_as_ushort(h1),
                              __bfloat16_as_ushort(h2), __bfloat16_as_ushort(h3));
    ushort4 pl = make_ushort4(__bfloat16_as_ushort(l0), __bfloat16_as_ushort(l1),
                              __bfloat16_as_ushort(l2), __bfloat16_as_ushort(l3));
    size_t base = (size_t)row * (3 * (size_t)K);
    int hi2 = bside ? 2 * K : K;
    int lo1 = bside ? K : 2 * K;
    *(ushort4*)(Y + base + col)       = ph;
    *(ushort4*)(Y + base + hi2 + col) = ph;
    *(ushort4*)(Y + base + lo1 + col) = pl;
}

__global__ __launch_bounds__(256) void convert_all(
    const float* __restrict__ embs, const float* __restrict__ Wq,
    const float* __restrict__ Wk,   const float* __restrict__ Wv,
    __nv_bfloat16* __restrict__ ea, u16* __restrict__ eh,
    __nv_bfloat16* __restrict__ Wqb, __nv_bfloat16* __restrict__ Wkb,
    u16* __restrict__ Wvh)
{
    const int i = blockIdx.x * blockDim.x + threadIdx.x;
    if (i < E4) {
        const int e = i * 4;
        const int row = e >> 10, col = e & 1023;
        float4 v = *(const float4*)(embs + e);
        split3_store(v, ea, row, col, DIN, 0);
        ushort4 h;
        h.x = __half_as_ushort(__float2half_rn(v.x));
        h.y = __half_as_ushort(__float2half_rn(v.y));
        h.z = __half_as_ushort(__float2half_rn(v.z));
        h.w = __half_as_ushort(__float2half_rn(v.w));
        *(ushort4*)(eh + e) = h;
    } else if (i < E4 + W4) {
        const int e = (i - E4) * 4;
        const int row = e >> 10, col = e & 1023;
        split3_store(*(const float4*)(Wq + e), Wqb, row, col, DIN, 1);
    } else if (i < E4 + 2 * W4) {
        const int e = (i - E4 - W4) * 4;
        const int row = e >> 10, col = e & 1023;
        split3_store(*(const float4*)(Wk + e), Wkb, row, col, DIN, 1);
    } else if (i < E4 + 3 * W4) {
        const int e = (i - E4 - 2 * W4) * 4;
        float4 v = *(const float4*)(Wv + e);
        ushort4 h;
        h.x = __half_as_ushort(__float2half_rn(v.x));
        h.y = __half_as_ushort(__float2half_rn(v.y));
        h.z = __half_as_ushort(__float2half_rn(v.z));
        h.w = __half_as_ushort(__float2half_rn(v.w));
        *(ushort4*)(Wvh + e) = h;
    }
}

// ---------------------------------------------------------------------------
// Common GEMM building blocks
// ---------------------------------------------------------------------------
#define BM 128
#define BK 64

__device__ __forceinline__ uint32_t smem_u32(const void* p) {
    uint32_t a;
    asm("{ .reg .u64 t; cvta.to.shared.u64 t, %1; cvt.u32.u64 %0, t; }"
        : "=r"(a) : "l"(p));
    return a;
}
#define SWZ(off) ((off) ^ (((off) >> 3) & 0x70))

__device__ __forceinline__ void cp16(uint32_t dst, const void* src) {
    asm volatile("cp.async.cg.shared.global [%0], [%1], 16;"
                 :: "r"(dst), "l"(src) : "memory");
}
__device__ __forceinline__ void ldsm_x4(uint32_t* r, uint32_t addr) {
    asm volatile("ldmatrix.sync.aligned.m8n8.x4.shared.b16 {%0,%1,%2,%3}, [%4];"
                 : "=r"(r[0]), "=r"(r[1]), "=r"(r[2]), "=r"(r[3]) : "r"(addr));
}
template<bool FP16>
__device__ __forceinline__ void mma16816(float* d, const uint32_t* a, const uint32_t* b);
template<>
__device__ __forceinline__ void mma16816<false>(float* d, const uint32_t* a, const uint32_t* b) {
    asm volatile(
        "mma.sync.aligned.m16n8k16.row.col.f32.bf16.bf16.f32 "
        "{%0,%1,%2,%3}, {%4,%5,%6,%7}, {%8,%9}, {%0,%1,%2,%3};"
        : "+f"(d[0]), "+f"(d[1]), "+f"(d[2]), "+f"(d[3])
        : "r"(a[0]), "r"(a[1]), "r"(a[2]), "r"(a[3]), "r"(b[0]), "r"(b[1]));
}
template<>
__device__ __forceinline__ void mma16816<true>(float* d, const uint32_t* a, const uint32_t* b) {
    asm volatile(
        "mma.sync.aligned.m16n8k16.row.col.f32.f16.f16.f32 "
        "{%0,%1,%2,%3}, {%4,%5,%6,%7}, {%8,%9}, {%0,%1,%2,%3};"
        : "+f"(d[0]), "+f"(d[1]), "+f"(d[2]), "+f"(d[3])
        : "r"(a[0]), "r"(a[1]), "r"(a[2]), "r"(a[3]), "r"(b[0]), "r"(b[1]));
}

// ---------------------------------------------------------------------------
// General 16-bit NT GEMM (non-persistent), as in round 10.
// ---------------------------------------------------------------------------
template<int BN_T, bool FP16, int OCC>
__global__ __launch_bounds__(128, OCC) void gemm_nt(
    const u16* __restrict__ A,
    const u16* __restrict__ B,
    const u16* __restrict__ B2,
    const float* __restrict__ biasCol,
    const float* __restrict__ biasCol2,
    const float* __restrict__ biasRow,
    const float* __restrict__ rowScale,
    float* __restrict__ Cf,
    u16*   __restrict__ Ch,
    u16*   __restrict__ Cs,
    u16*   __restrict__ Cs2,
    int o2, int dupHi, int dupHi2,
    int nsplit, int Nn, int Kg)
{
    constexpr int NI  = BN_T / 16;
    constexpr int NG  = NI / 2;
    constexpr int ASZ = BM * 128;
    constexpr int BSZ = BN_T * 128;
    constexpr int STG = ASZ + BSZ;
    constexpr int A_CH = 8;
    constexpr int B_CH = BN_T / 16;

    extern __shared__ __align__(128) char smem[];
    const uint32_t sbase = smem_u32(smem);

    const int tid  = threadIdx.x;
    const int lane = tid & 31;
    const int wid  = tid >> 5;
    const int wm   = wid >> 1;
    const int wn   = wid & 1;
    const int bm = blockIdx.y * BM;
    int bn = blockIdx.x * BN_T;
    int dup = dupHi;

    if (nsplit && bn >= nsplit) {
        B = B2; biasCol = biasCol2; Cs = Cs2; dup = dupHi2;
        bn -= nsplit;
    }

    const int KT = Kg / BK;

    float acc[4][NI][4];
    #pragma unroll
    for (int i = 0; i < 4; i++)
        #pragma unroll
        for (int j = 0; j < NI; j++)
            #pragma unroll
            for (int q = 0; q < 4; q++) acc[i][j][q] = 0.0f;

    const int lcb = (tid & 7) * 16;

    auto load_tile = [&](int kt, int buf) {
        const int k0 = kt * BK;
        const uint32_t sA = sbase + buf * STG;
        const uint32_t sB = sA + ASZ;
        #pragma unroll
        for (int r = 0; r < A_CH; r++) {
            const int row = (tid + r * 128) >> 3;
            cp16(sA + SWZ((uint32_t)(row * 128 + lcb)),
                 A + (size_t)(bm + row) * Kg + k0 + lcb / 2);
        }
        #pragma unroll
        for (int r = 0; r < B_CH; r++) {
            const int row = (tid + r * 128) >> 3;
            cp16(sB + SWZ((uint32_t)(row * 128 + lcb)),
                 B + (size_t)(bn + row) * Kg + k0 + lcb / 2);
        }
        asm volatile("cp.async.commit_group;" ::: "memory");
    };

    load_tile(0, 0);
    load_tile(1, 1);

    const int a_row = wm * 64 + (lane & 15);
    const int a_kb  = (lane >> 4) * 16;
    const int b_row = wn * (BN_T / 2) + (lane & 7) + ((lane >> 4) & 1) * 8;
    const int b_kb  = ((lane >> 3) & 1) * 16;

    uint32_t af[2][4][4], bq[2][NG][4];

    for (int kt = 0; kt < KT; kt++) {
        if (kt < KT - 1) asm volatile("cp.async.wait_group 1;" ::: "memory");
        else             asm volatile("cp.async.wait_group 0;" ::: "memory");
        __syncthreads();

        if (kt + 2 < KT) load_tile(kt + 2, (kt + 2) % 3);

        const uint32_t sA = sbase + (kt % 3) * STG;
        const uint32_t sB = sA + ASZ;

        #pragma unroll
        for (int mi = 0; mi < 4; mi++)
            ldsm_x4(af[0][mi], sA + SWZ((uint32_t)((a_row + mi * 16) * 128 + a_kb)));
        #pragma unroll
        for (int ng = 0; ng < NG; ng++)
            ldsm_x4(bq[0][ng], sB + SWZ((uint32_t)((b_row + ng * 16) * 128 + b_kb)));

        #pragma unroll
        for (int ks = 0; ks < 4; ks++) {
            const int cur = ks & 1, nxt = cur ^ 1;
            if (ks < 3) {
                #pragma unroll
                for (int mi = 0; mi < 4; mi++)
                    ldsm_x4(af[nxt][mi],
                            sA + SWZ((uint32_t)((a_row + mi * 16) * 128 + (ks + 1) * 32 + a_kb)));
                #pragma unroll
                for (int ng = 0; ng < NG; ng++)
                    ldsm_x4(bq[nxt][ng],
                            sB + SWZ((uint32_t)((b_row + ng * 16) * 128 + (ks + 1) * 32 + b_kb)));
            }
            #pragma unroll
            for (int mi = 0; mi < 4; mi++)
                #pragma unroll
                for (int ni = 0; ni < NI; ni++)
                    mma16816<FP16>(acc[mi][ni], af[cur][mi], &bq[cur][ni >> 1][(ni & 1) * 2]);
        }
    }

    #pragma unroll
    for (int mi = 0; mi < 4; mi++) {
        const int r0 = bm + wm * 64 + mi * 16 + (lane >> 2);
        const float rs0 = rowScale ? rowScale[r0]     : 1.0f;
        const float rs1 = rowScale ? rowScale[r0 + 8] : 1.0f;
        #pragma unroll
        for (int ni = 0; ni < NI; ni++) {
            const int c = bn + wn * (BN_T / 2) + ni * 8 + (lane & 3) * 2;
            float2 v0 = make_float2(acc[mi][ni][0] * rs0, acc[mi][ni][1] * rs0);
            float2 v1 = make_float2(acc[mi][ni][2] * rs1, acc[mi][ni][3] * rs1);
            if (biasCol) {
                const float2 bc = *(const float2*)(biasCol + c);
                v0.x += bc.x; v0.y += bc.y; v1.x += bc.x; v1.y += bc.y;
            }
            if (biasRow) {
                const float br0 = biasRow[r0];
                const float br1 = biasRow[r0 + 8];
                v0.x += br0; v0.y += br0; v1.x += br1; v1.y += br1;
            }
            if (Cf) {
                *(float2*)(Cf + (size_t)r0 * Nn + c)       = v0;
                *(float2*)(Cf + (size_t)(r0 + 8) * Nn + c) = v1;
            } else if (Ch) {
                #pragma unroll
                for (int rr = 0; rr < 2; rr++) {
                    const float2 v = rr ? v1 : v0;
                    ushort2 h;
                    h.x = __half_as_ushort(__float2half_rn(v.x));
                    h.y = __half_as_ushort(__float2half_rn(v.y));
                    *(ushort2*)(Ch + (size_t)(r0 + rr * 8) * Nn + c) = h;
                }
            } else {
                #pragma unroll
                for (int rr = 0; rr < 2; rr++) {
                    const float2 v = rr ? v1 : v0;
                    const size_t base = (size_t)(r0 + rr * 8) * (2 * (size_t)Nn) + c;
                    __half hx = __float2half_rn(v.x);
                    __half hy = __float2half_rn(v.y);
                    ushort2 ph = make_ushort2(__half_as_ushort(hx), __half_as_ushort(hy));
                    ushort2 p2;
                    if (dup) {
                        p2 = ph;
                    } else {
                        __half lx = __float2half_rn(v.x - __half2float(hx));
                        __half ly = __float2half_rn(v.y - __half2float(hy));
                        p2 = make_ushort2(__half_as_ushort(lx), __half_as_ushort(ly));
                    }
                    *(ushort2*)(Cs + base)      = ph;
                    *(ushort2*)(Cs + base + o2) = p2;
                }
            }
        }
    }
}

// ---------------------------------------------------------------------------
// Persistent fp16 NT GEMM for S: BN=128, 2 CTAs/SM, fp32 out, no bias.
// grid = 296 CTAs; each loops tiles t = bid, bid+296, ... over nTiles.
// ---------------------------------------------------------------------------
__global__ __launch_bounds__(128, 2) void gemm_s_persist(
    const u16* __restrict__ A,      // Qa [M, Kg]
    const u16* __restrict__ B,      // Kb [N, Kg]
    float* __restrict__ Cf,         // S  [M, N]
    int nTilesX, int nTiles, int Nn, int Kg)
{
    constexpr int BN_T = 128;
    constexpr int NI  = 8;
    constexpr int NG  = 4;
    constexpr int ASZ = BM * 128;
    constexpr int BSZ = BN_T * 128;
    constexpr int STG = ASZ + BSZ;

    extern __shared__ __align__(128) char smem[];
    const uint32_t sbase = smem_u32(smem);

    const int tid  = threadIdx.x;
    const int lane = tid & 31;
    const int wid  = tid >> 5;
    const int wm   = wid >> 1;
    const int wn   = wid & 1;
    const int lcb  = (tid & 7) * 16;

    const int KT = Kg / BK;

    const int a_row = wm * 64 + (lane & 15);
    const int a_kb  = (lane >> 4) * 16;
    const int b_row = wn * 64 + (lane & 7) + ((lane >> 4) & 1) * 8;
    const int b_kb  = ((lane >> 3) & 1) * 16;

    for (int t = blockIdx.x; t < nTiles; t += gridDim.x) {
        const int bm = (t / nTilesX) * BM;
        const int bn = (t % nTilesX) * BN_T;

        float acc[4][NI][4];
        #pragma unroll
        for (int i = 0; i < 4; i++)
            #pragma unroll
            for (int j = 0; j < NI; j++)
                #pragma unroll
                for (int q = 0; q < 4; q++) acc[i][j][q] = 0.0f;

        auto load_tile = [&](int kt, int buf) {
            const int k0 = kt * BK;
            const uint32_t sA = sbase + buf * STG;
            const uint32_t sB = sA + ASZ;
            #pragma unroll
            for (int r = 0; r < 8; r++) {
                const int row = (tid + r * 128) >> 3;
                cp16(sA + SWZ((uint32_t)(row * 128 + lcb)),
                     A + (size_t)(bm + row) * Kg + k0 + lcb / 2);
            }
            #pragma unroll
            for (int r = 0; r < 8; r++) {
                const int row = (tid + r * 128) >> 3;
                cp16(sB + SWZ((uint32_t)(row * 128 + lcb)),
                     B + (size_t)(bn + row) * Kg + k0 + lcb / 2);
            }
            asm volatile("cp.async.commit_group;" ::: "memory");
        };

        load_tile(0, 0);
        load_tile(1, 1);

        uint32_t af[2][4][4], bq[2][NG][4];

        for (int kt = 0; kt < KT; kt++) {
            if (kt < KT - 1) asm volatile("cp.async.wait_group 1;" ::: "memory");
            else             asm volatile("cp.async.wait_group 0;" ::: "memory");
            __syncthreads();

            if (kt + 2 < KT) load_tile(kt + 2, (kt + 2) % 3);

            const uint32_t sA = sbase + (kt % 3) * STG;
            const uint32_t sB = sA + ASZ;

            #pragma unroll
            for (int mi = 0; mi < 4; mi++)
                ldsm_x4(af[0][mi], sA + SWZ((uint32_t)((a_row + mi * 16) * 128 + a_kb)));
            #pragma unroll
            for (int ng = 0; ng < NG; ng++)
                ldsm_x4(bq[0][ng], sB + SWZ((uint32_t)((b_row + ng * 16) * 128 + b_kb)));

            #pragma unroll
            for (int ks = 0; ks < 4; ks++) {
                const int cur = ks & 1, nxt = cur ^ 1;
                if (ks < 3) {
                    #pragma unroll
                    for (int mi = 0; mi < 4; mi++)
                        ldsm_x4(af[nxt][mi],
                                sA + SWZ((uint32_t)((a_row + mi * 16) * 128 + (ks + 1) * 32 + a_kb)));
                    #pragma unroll
                    for (int ng = 0; ng < NG; ng++)
                        ldsm_x4(bq[nxt][ng],
                                sB + SWZ((uint32_t)((b_row + ng * 16) * 128 + (ks + 1) * 32 + b_kb)));
                }
                #pragma unroll
                for (int mi = 0; mi < 4; mi++)
                    #pragma unroll
                    for (int ni = 0; ni < NI; ni++)
                        mma16816<true>(acc[mi][ni], af[cur][mi], &bq[cur][ni >> 1][(ni & 1) * 2]);
            }
        }

        // epilogue: fp32 store
        #pragma unroll
        for (int mi = 0; mi < 4; mi++) {
            const int r0 = bm + wm * 64 + mi * 16 + (lane >> 2);
            #pragma unroll
            for (int ni = 0; ni < NI; ni++) {
                const int c = bn + wn * 64 + ni * 8 + (lane & 3) * 2;
                *(float2*)(Cf + (size_t)r0 * Nn + c) =
                    make_float2(acc[mi][ni][0], acc[mi][ni][1]);
                *(float2*)(Cf + (size_t)(r0 + 8) * Nn + c) =
                    make_float2(acc[mi][ni][2], acc[mi][ni][3]);
            }
        }
        // ensure all warps done with smem before next tile's loads
        __syncthreads();
    }
}

// ---------------------------------------------------------------------------
// Row softmax (unnormalized): P = fp16(exp(s - max)), rowInv = 1/sum.
// ---------------------------------------------------------------------------
__global__ __launch_bounds__(256) void softmax_half(
    const float* __restrict__ S, u16* __restrict__ P, float* __restrict__ rowInv)
{
    __shared__ float buf[NSEQ];
    __shared__ float red[8];

    const int tid = threadIdx.x;
    const int lane = tid & 31;
    const int warp = tid >> 5;
    const float* p = S + (size_t)blockIdx.x * NSEQ;
    u16* q = P + (size_t)blockIdx.x * NSEQ;

    float m = -CUDART_INF_F;
    for (int i = tid * 4; i < NSEQ; i += 256 * 4) {
        float4 v = *(const float4*)(p + i);
        *(float4*)&buf[i] = v;
        m = fmaxf(m, fmaxf(fmaxf(v.x, v.y), fmaxf(v.z, v.w)));
    }
    #pragma unroll
    for (int o = 16; o > 0; o >>= 1) m = fmaxf(m, __shfl_xor_sync(0xffffffffu, m, o));
    if (lane == 0) red[warp] = m;
    __syncthreads();
    if (warp == 0) {
        float v = (lane < 8) ? red[lane] : -CUDART_INF_F;
        #pragma unroll
        for (int o = 4; o > 0; o >>= 1) v = fmaxf(v, __shfl_xor_sync(0xffffffffu, v, o));
        if (lane == 0) red[0] = v;
    }
    __syncthreads();
    m = red[0];
    __syncthreads();

    float s = 0.0f;
    for (int i = tid * 4; i < NSEQ; i += 256 * 4) {
        float4 v = *(const float4*)&buf[i];
        v.x = __expf(v.x - m); v.y = __expf(v.y - m);
        v.z = __expf(v.z - m); v.w = __expf(v.w - m);
        s += v.x + v.y + v.z + v.w;
        ushort4 h;
        h.x = __half_as_ushort(__float2half_rn(v.x));
        h.y = __half_as_ushort(__float2half_rn(v.y));
        h.z = __half_as_ushort(__float2half_rn(v.z));
        h.w = __half_as_ushort(__float2half_rn(v.w));
        *(ushort4*)(q + i) = h;
    }
    #pragma unroll
    for (int o = 16; o > 0; o >>= 1) s += __shfl_xor_sync(0xffffffffu, s, o);
    if (lane == 0) red[warp] = s;
    __syncthreads();
    if (warp == 0) {
        float v = (lane < 8) ? red[lane] : 0.0f;
        #pragma unroll
        for (int o = 4; o > 0; o >>= 1) v += __shfl_xor_sync(0xffffffffu, v, o);
        if (lane == 0) rowInv[blockIdx.x] = 1.0f / v;
    }
}

// ---------------------------------------------------------------------------
// Launch
// ---------------------------------------------------------------------------
extern "C" void kernel_launch(void* const* d_in, const int* in_sizes, int n_in,
                              void* d_out, int out_size)
{
    const float* embs = (const float*)d_in[0];
    const float* Wq   = (const float*)d_in[1];
    const float* bq   = (const float*)d_in[2];
    const float* Wk   = (const float*)d_in[3];
    const float* bk   = (const float*)d_in[4];
    const float* Wv   = (const float*)d_in[5];
    const float* bv   = (const float*)d_in[6];
    float* out = (float*)d_out;

    float *S, *rowInv;
    __nv_bfloat16 *ea, *Wqb, *Wkb;
    u16 *eh, *Wvh, *Qa, *Kb, *Ph, *Vth;
    cudaGetSymbolAddress((void**)&S,      g_S);
    cudaGetSymbolAddress((void**)&rowInv, g_rowInv);
    cudaGetSymbolAddress((void**)&ea,  g_ea);
    cudaGetSymbolAddress((void**)&Wqb, g_Wqb);
    cudaGetSymbolAddress((void**)&Wkb, g_Wkb);
    cudaGetSymbolAddress((void**)&eh,  g_eh);
    cudaGetSymbolAddress((void**)&Wvh, g_Wvh);
    cudaGetSymbolAddress((void**)&Qa,  g_Qa);
    cudaGetSymbolAddress((void**)&Kb,  g_Kb);
    cudaGetSymbolAddress((void**)&Ph,  g_Ph);
    cudaGetSymbolAddress((void**)&Vth, g_Vth);

    const int smem128 = 3 * (128 + 128) * 128;   // 96 KB
    const int smem64  = 3 * (128 + 64) * 128;    // 72 KB
    cudaFuncSetAttribute((const void*)gemm_nt<128, false, 2>, cudaFuncAttributeMaxDynamicSharedMemorySize, smem128);
    cudaFuncSetAttribute((const void*)gemm_nt<64, true, 3>,   cudaFuncAttributeMaxDynamicSharedMemorySize, smem64);
    cudaFuncSetAttribute((const void*)gemm_s_persist,         cudaFuncAttributeMaxDynamicSharedMemorySize, smem128);

    dim3 blk(128);
    dim3 blk256(256);

    // 1. merged input conversions
    convert_all<<<(E4 + 3 * W4) / 256, blk256>>>(embs, Wq, Wk, Wv, ea, eh, Wqb, Wkb, Wvh);

    // 2. fused Q+K projection (bf16 3-term in, fp16 2-seg out)
    gemm_nt<128, false, 2><<<dim3(2 * HID / 128, NSEQ / BM), blk, smem128>>>(
        (const u16*)ea, (const u16*)Wqb, (const u16*)Wkb,
        bq, bk, nullptr, nullptr,
        nullptr, nullptr, Qa, Kb,
        HID, 0, 1, HID, HID, 3 * DIN);

    // 3. Vt projection (fp16 1-term), 3 CTAs/SM
    gemm_nt<64, true, 3><<<dim3(NSEQ / 64, HID / BM), blk, smem64>>>(
        Wvh, eh, nullptr,
        nullptr, nullptr, bv, nullptr,
        nullptr, Vth, nullptr, nullptr,
        0, 0, 0, 0, NSEQ, DIN);

    // 4. S = Q @ K^T (fp16 2-term), persistent: 296 CTAs over 32x32 tiles
    gemm_s_persist<<<296, blk, smem128>>>(
        Qa, Kb, S, NSEQ / 128, (NSEQ / 128) * (NSEQ / 128), NSEQ, 2 * HID);

    // 5. softmax -> fp16 exp + rowInv
    softmax_half<<<NSEQ, blk256>>>(S, Ph, rowInv);

    // 6. out = (P @ Vt^T) * rowInv (fp16 1-term), 3 CTAs/SM
    gemm_nt<64, true, 3><<<dim3(HID / 64, NSEQ / BM), blk, smem64>>>(
        Ph, Vth, nullptr,
        nullptr, nullptr, nullptr, rowInv,
        out, nullptr, nullptr, nullptr,
        0, 0, 0, 0, HID, NSEQ);
}

// round 14
// speedup vs baseline: 1.5391x; 1.5391x over previous
#include <cuda_runtime.h>
#include <cuda_bf16.h>
#include <cuda_fp16.h>
#include <math_constants.h>
#include <cstdint>

#define NSEQ 4096
#define DIN  1024
#define HID  512

typedef unsigned short u16;

// ---------------------------------------------------------------------------
// Device scratch
// ---------------------------------------------------------------------------
__device__ float g_S [(size_t)NSEQ * NSEQ];                // 64 MB logits
__device__ float g_rowInv[NSEQ];                           // 1/Z per row

__device__ __nv_bfloat16 g_ea [(size_t)NSEQ * 3 * DIN];    // embs bf16 a3-form
__device__ __nv_bfloat16 g_Wqb[(size_t)HID  * 3 * DIN];    // Wq  bf16 b3-form
__device__ __nv_bfloat16 g_Wkb[(size_t)HID  * 3 * DIN];    // Wk  bf16 b3-form
__device__ u16 g_eh [(size_t)NSEQ * DIN];                  // embs fp16
__device__ u16 g_Wvh[(size_t)HID  * DIN];                  // Wv   fp16
__device__ u16 g_Qa [(size_t)NSEQ * 2 * HID];              // [Qh | Ql] fp16
__device__ u16 g_Kb [(size_t)NSEQ * 2 * HID];              // [Kh | Kh] fp16
__device__ u16 g_Ph [(size_t)NSEQ * NSEQ];                 // exp(s-m) fp16, 32 MB
__device__ u16 g_Vth[(size_t)HID  * NSEQ];                 // Vt fp16

// ---------------------------------------------------------------------------
// Merged input conversions (one launch).
// ---------------------------------------------------------------------------
#define E4  (NSEQ * DIN / 4)            // 1048576
#define W4  (HID * DIN / 4)             // 131072

__device__ __forceinline__ void split3_store(
    float4 v, __nv_bfloat16* Y, int row, int col, int K, int bside)
{
    __nv_bfloat16 h0 = __float2bfloat16_rn(v.x);
    __nv_bfloat16 h1 = __float2bfloat16_rn(v.y);
    __nv_bfloat16 h2 = __float2bfloat16_rn(v.z);
    __nv_bfloat16 h3 = __float2bfloat16_rn(v.w);
    __nv_bfloat16 l0 = __float2bfloat16_rn(v.x - __bfloat162float(h0));
    __nv_bfloat16 l1 = __float2bfloat16_rn(v.y - __bfloat162float(h1));
    __nv_bfloat16 l2 = __float2bfloat16_rn(v.z - __bfloat162float(h2));
    __nv_bfloat16 l3 = __float2bfloat16_rn(v.w - __bfloat162float(h3));
    ushort4 ph = make_ushort4(__bfloat16_as_ushort(h0), __bfloat16_as_ushort(h1),
                              __bfloat16_as_ushort(h2), __bfloat16_as_ushort(h3));
    ushort4 pl = make_ushort4(__bfloat16_as_ushort(l0), __bfloat16_as_ushort(l1),
                              __bfloat16_as_ushort(l2), __bfloat16_as_ushort(l3));
    size_t base = (size_t)row * (3 * (size_t)K);
    int hi2 = bside ? 2 * K : K;
    int lo1 = bside ? K : 2 * K;
    *(ushort4*)(Y + base + col)       = ph;
    *(ushort4*)(Y + base + hi2 + col) = ph;
    *(ushort4*)(Y + base + lo1 + col) = pl;
}

__global__ __launch_bounds__(256) void convert_all(
    const float* __restrict__ embs, const float* __restrict__ Wq,
    const float* __restrict__ Wk,   const float* __restrict__ Wv,
    __nv_bfloat16* __restrict__ ea, u16* __restrict__ eh,
    __nv_bfloat16* __restrict__ Wqb, __nv_bfloat16* __restrict__ Wkb,
    u16* __restrict__ Wvh)
{
    const int i = blockIdx.x * blockDim.x + threadIdx.x;
    if (i < E4) {
        const int e = i * 4;
        const int row = e >> 10, col = e & 1023;
        float4 v = *(const float4*)(embs + e);
        split3_store(v, ea, row, col, DIN, 0);
        ushort4 h;
        h.x = __half_as_ushort(__float2half_rn(v.x));
        h.y = __half_as_ushort(__float2half_rn(v.y));
        h.z = __half_as_ushort(__float2half_rn(v.z));
        h.w = __half_as_ushort(__float2half_rn(v.w));
        *(ushort4*)(eh + e) = h;
    } else if (i < E4 + W4) {
        const int e = (i - E4) * 4;
        const int row = e >> 10, col = e & 1023;
        split3_store(*(const float4*)(Wq + e), Wqb, row, col, DIN, 1);
    } else if (i < E4 + 2 * W4) {
        const int e = (i - E4 - W4) * 4;
        const int row = e >> 10, col = e & 1023;
        split3_store(*(const float4*)(Wk + e), Wkb, row, col, DIN, 1);
    } else if (i < E4 + 3 * W4) {
        const int e = (i - E4 - 2 * W4) * 4;
        float4 v = *(const float4*)(Wv + e);
        ushort4 h;
        h.x = __half_as_ushort(__float2half_rn(v.x));
        h.y = __half_as_ushort(__float2half_rn(v.y));
        h.z = __half_as_ushort(__float2half_rn(v.z));
        h.w = __half_as_ushort(__float2half_rn(v.w));
        *(ushort4*)(Wvh + e) = h;
    }
}

// ---------------------------------------------------------------------------
// 16-bit NT GEMM, mma.sync m16n8k16. 128 threads, 2x2 warps, warp tile
// 64 x (BN_T/2). 3-stage cp.async pipeline, reg-fragment double buffer.
// ---------------------------------------------------------------------------
#define BM 128
#define BK 64

__device__ __forceinline__ uint32_t smem_u32(const void* p) {
    uint32_t a;
    asm("{ .reg .u64 t; cvta.to.shared.u64 t, %1; cvt.u32.u64 %0, t; }"
        : "=r"(a) : "l"(p));
    return a;
}
#define SWZ(off) ((off) ^ (((off) >> 3) & 0x70))

__device__ __forceinline__ void cp16(uint32_t dst, const void* src) {
    asm volatile("cp.async.cg.shared.global [%0], [%1], 16;"
                 :: "r"(dst), "l"(src) : "memory");
}
__device__ __forceinline__ void ldsm_x4(uint32_t* r, uint32_t addr) {
    asm volatile("ldmatrix.sync.aligned.m8n8.x4.shared.b16 {%0,%1,%2,%3}, [%4];"
                 : "=r"(r[0]), "=r"(r[1]), "=r"(r[2]), "=r"(r[3]) : "r"(addr));
}
template<bool FP16>
__device__ __forceinline__ void mma16816(float* d, const uint32_t* a, const uint32_t* b);
template<>
__device__ __forceinline__ void mma16816<false>(float* d, const uint32_t* a, const uint32_t* b) {
    asm volatile(
        "mma.sync.aligned.m16n8k16.row.col.f32.bf16.bf16.f32 "
        "{%0,%1,%2,%3}, {%4,%5,%6,%7}, {%8,%9}, {%0,%1,%2,%3};"
        : "+f"(d[0]), "+f"(d[1]), "+f"(d[2]), "+f"(d[3])
        : "r"(a[0]), "r"(a[1]), "r"(a[2]), "r"(a[3]), "r"(b[0]), "r"(b[1]));
}
template<>
__device__ __forceinline__ void mma16816<true>(float* d, const uint32_t* a, const uint32_t* b) {
    asm volatile(
        "mma.sync.aligned.m16n8k16.row.col.f32.f16.f16.f32 "
        "{%0,%1,%2,%3}, {%4,%5,%6,%7}, {%8,%9}, {%0,%1,%2,%3};"
        : "+f"(d[0]), "+f"(d[1]), "+f"(d[2]), "+f"(d[3])
        : "r"(a[0]), "r"(a[1]), "r"(a[2]), "r"(a[3]), "r"(b[0]), "r"(b[1]));
}

template<int BN_T, bool FP16, int OCC>
__global__ __launch_bounds__(128, OCC) void gemm_nt(
    const u16* __restrict__ A,
    const u16* __restrict__ B,
    const u16* __restrict__ B2,
    const float* __restrict__ biasCol,
    const float* __restrict__ biasCol2,
    const float* __restrict__ biasRow,
    const float* __restrict__ rowScale,
    float* __restrict__ Cf,
    u16*   __restrict__ Ch,
    u16*   __restrict__ Cs,
    u16*   __restrict__ Cs2,
    int o2, int dupHi, int dupHi2,
    int nsplit, int Nn, int Kg)
{
    constexpr int NI  = BN_T / 16;
    constexpr int NG  = NI / 2;
    constexpr int ASZ = BM * 128;
    constexpr int BSZ = BN_T * 128;
    constexpr int STG = ASZ + BSZ;
    constexpr int A_CH = 8;
    constexpr int B_CH = BN_T / 16;

    extern __shared__ __align__(128) char smem[];
    const uint32_t sbase = smem_u32(smem);

    const int tid  = threadIdx.x;
    const int lane = tid & 31;
    const int wid  = tid >> 5;
    const int wm   = wid >> 1;
    const int wn   = wid & 1;
    const int bm = blockIdx.y * BM;
    int bn = blockIdx.x * BN_T;
    int dup = dupHi;

    if (nsplit && bn >= nsplit) {
        B = B2; biasCol = biasCol2; Cs = Cs2; dup = dupHi2;
        bn -= nsplit;
    }

    const int KT = Kg / BK;

    float acc[4][NI][4];
    #pragma unroll
    for (int i = 0; i < 4; i++)
        #pragma unroll
        for (int j = 0; j < NI; j++)
            #pragma unroll
            for (int q = 0; q < 4; q++) acc[i][j][q] = 0.0f;

    const int lcb = (tid & 7) * 16;

    auto load_tile = [&](int kt, int buf) {
        const int k0 = kt * BK;
        const uint32_t sA = sbase + buf * STG;
        const uint32_t sB = sA + ASZ;
        #pragma unroll
        for (int r = 0; r < A_CH; r++) {
            const int row = (tid + r * 128) >> 3;
            cp16(sA + SWZ((uint32_t)(row * 128 + lcb)),
                 A + (size_t)(bm + row) * Kg + k0 + lcb / 2);
        }
        #pragma unroll
        for (int r = 0; r < B_CH; r++) {
            const int row = (tid + r * 128) >> 3;
            cp16(sB + SWZ((uint32_t)(row * 128 + lcb)),
                 B + (size_t)(bn + row) * Kg + k0 + lcb / 2);
        }
        asm volatile("cp.async.commit_group;" ::: "memory");
    };

    load_tile(0, 0);
    load_tile(1, 1);

    const int a_row = wm * 64 + (lane & 15);
    const int a_kb  = (lane >> 4) * 16;
    const int b_row = wn * (BN_T / 2) + (lane & 7) + ((lane >> 4) & 1) * 8;
    const int b_kb  = ((lane >> 3) & 1) * 16;

    uint32_t af[2][4][4], bq[2][NG][4];

    for (int kt = 0; kt < KT; kt++) {
        if (kt < KT - 1) asm volatile("cp.async.wait_group 1;" ::: "memory");
        else             asm volatile("cp.async.wait_group 0;" ::: "memory");
        __syncthreads();

        if (kt + 2 < KT) load_tile(kt + 2, (kt + 2) % 3);

        const uint32_t sA = sbase + (kt % 3) * STG;
        const uint32_t sB = sA + ASZ;

        #pragma unroll
        for (int mi = 0; mi < 4; mi++)
            ldsm_x4(af[0][mi], sA + SWZ((uint32_t)((a_row + mi * 16) * 128 + a_kb)));
        #pragma unroll
        for (int ng = 0; ng < NG; ng++)
            ldsm_x4(bq[0][ng], sB + SWZ((uint32_t)((b_row + ng * 16) * 128 + b_kb)));

        #pragma unroll
        for (int ks = 0; ks < 4; ks++) {
            const int cur = ks & 1, nxt = cur ^ 1;
            if (ks < 3) {
                #pragma unroll
                for (int mi = 0; mi < 4; mi++)
                    ldsm_x4(af[nxt][mi],
                            sA + SWZ((uint32_t)((a_row + mi * 16) * 128 + (ks + 1) * 32 + a_kb)));
                #pragma unroll
                for (int ng = 0; ng < NG; ng++)
                    ldsm_x4(bq[nxt][ng],
                            sB + SWZ((uint32_t)((b_row + ng * 16) * 128 + (ks + 1) * 32 + b_kb)));
            }
            #pragma unroll
            for (int mi = 0; mi < 4; mi++)
                #pragma unroll
                for (int ni = 0; ni < NI; ni++)
                    mma16816<FP16>(acc[mi][ni], af[cur][mi], &bq[cur][ni >> 1][(ni & 1) * 2]);
        }
    }

    #pragma unroll
    for (int mi = 0; mi < 4; mi++) {
        const int r0 = bm + wm * 64 + mi * 16 + (lane >> 2);
        const float rs0 = rowScale ? rowScale[r0]     : 1.0f;
        const float rs1 = rowScale ? rowScale[r0 + 8] : 1.0f;
        #pragma unroll
        for (int ni = 0; ni < NI; ni++) {
            const int c = bn + wn * (BN_T / 2) + ni * 8 + (lane & 3) * 2;
            float2 v0 = make_float2(acc[mi][ni][0] * rs0, acc[mi][ni][1] * rs0);
            float2 v1 = make_float2(acc[mi][ni][2] * rs1, acc[mi][ni][3] * rs1);
            if (biasCol) {
                const float2 bc = *(const float2*)(biasCol + c);
                v0.x += bc.x; v0.y += bc.y; v1.x += bc.x; v1.y += bc.y;
            }
            if (biasRow) {
                const float br0 = biasRow[r0];
                const float br1 = biasRow[r0 + 8];
                v0.x += br0; v0.y += br0; v1.x += br1; v1.y += br1;
            }
            if (Cf) {
                *(float2*)(Cf + (size_t)r0 * Nn + c)       = v0;
                *(float2*)(Cf + (size_t)(r0 + 8) * Nn + c) = v1;
            } else if (Ch) {
                #pragma unroll
                for (int rr = 0; rr < 2; rr++) {
                    const float2 v = rr ? v1 : v0;
                    ushort2 h;
                    h.x = __half_as_ushort(__float2half_rn(v.x));
                    h.y = __half_as_ushort(__float2half_rn(v.y));
                    *(ushort2*)(Ch + (size_t)(r0 + rr * 8) * Nn + c) = h;
                }
            } else {
                #pragma unroll
                for (int rr = 0; rr < 2; rr++) {
                    const float2 v = rr ? v1 : v0;
                    const size_t base = (size_t)(r0 + rr * 8) * (2 * (size_t)Nn) + c;
                    __half hx = __float2half_rn(v.x);
                    __half hy = __float2half_rn(v.y);
                    ushort2 ph = make_ushort2(__half_as_ushort(hx), __half_as_ushort(hy));
                    ushort2 p2;
                    if (dup) {
                        p2 = ph;
                    } else {
                        __half lx = __float2half_rn(v.x - __half2float(hx));
                        __half ly = __float2half_rn(v.y - __half2float(hy));
                        p2 = make_ushort2(__half_as_ushort(lx), __half_as_ushort(ly));
                    }
                    *(ushort2*)(Cs + base)      = ph;
                    *(ushort2*)(Cs + base + o2) = p2;
                }
            }
        }
    }
}

// ---------------------------------------------------------------------------
// Row softmax (unnormalized): P = fp16(exp(s - max)), rowInv = 1/sum.
// ---------------------------------------------------------------------------
__global__ __launch_bounds__(256) void softmax_half(
    const float* __restrict__ S, u16* __restrict__ P, float* __restrict__ rowInv)
{
    __shared__ float buf[NSEQ];
    __shared__ float red[8];

    const int tid = threadIdx.x;
    const int lane = tid & 31;
    const int warp = tid >> 5;
    const float* p = S + (size_t)blockIdx.x * NSEQ;
    u16* q = P + (size_t)blockIdx.x * NSEQ;

    float m = -CUDART_INF_F;
    for (int i = tid * 4; i < NSEQ; i += 256 * 4) {
        float4 v = *(const float4*)(p + i);
        *(float4*)&buf[i] = v;
        m = fmaxf(m, fmaxf(fmaxf(v.x, v.y), fmaxf(v.z, v.w)));
    }
    #pragma unroll
    for (int o = 16; o > 0; o >>= 1) m = fmaxf(m, __shfl_xor_sync(0xffffffffu, m, o));
    if (lane == 0) red[warp] = m;
    __syncthreads();
    if (warp == 0) {
        float v = (lane < 8) ? red[lane] : -CUDART_INF_F;
        #pragma unroll
        for (int o = 4; o > 0; o >>= 1) v = fmaxf(v, __shfl_xor_sync(0xffffffffu, v, o));
        if (lane == 0) red[0] = v;
    }
    __syncthreads();
    m = red[0];
    __syncthreads();

    float s = 0.0f;
    for (int i = tid * 4; i < NSEQ; i += 256 * 4) {
        float4 v = *(const float4*)&buf[i];
        v.x = __expf(v.x - m); v.y = __expf(v.y - m);
        v.z = __expf(v.z - m); v.w = __expf(v.w - m);
        s += v.x + v.y + v.z + v.w;
        ushort4 h;
        h.x = __half_as_ushort(__float2half_rn(v.x));
        h.y = __half_as_ushort(__float2half_rn(v.y));
        h.z = __half_as_ushort(__float2half_rn(v.z));
        h.w = __half_as_ushort(__float2half_rn(v.w));
        *(ushort4*)(q + i) = h;
    }
    #pragma unroll
    for (int o = 16; o > 0; o >>= 1) s += __shfl_xor_sync(0xffffffffu, s, o);
    if (lane == 0) red[warp] = s;
    __syncthreads();
    if (warp == 0) {
        float v = (lane < 8) ? red[lane] : 0.0f;
        #pragma unroll
        for (int o = 4; o > 0; o >>= 1) v += __shfl_xor_sync(0xffffffffu, v, o);
        if (lane == 0) rowInv[blockIdx.x] = 1.0f / v;
    }
}

// ---------------------------------------------------------------------------
// Launch
// ---------------------------------------------------------------------------
extern "C" void kernel_launch(void* const* d_in, const int* in_sizes, int n_in,
                              void* d_out, int out_size)
{
    const float* embs = (const float*)d_in[0];
    const float* Wq   = (const float*)d_in[1];
    const float* bq   = (const float*)d_in[2];
    const float* Wk   = (const float*)d_in[3];
    const float* bk   = (const float*)d_in[4];
    const float* Wv   = (const float*)d_in[5];
    const float* bv   = (const float*)d_in[6];
    float* out = (float*)d_out;

    float *S, *rowInv;
    __nv_bfloat16 *ea, *Wqb, *Wkb;
    u16 *eh, *Wvh, *Qa, *Kb, *Ph, *Vth;
    cudaGetSymbolAddress((void**)&S,      g_S);
    cudaGetSymbolAddress((void**)&rowInv, g_rowInv);
    cudaGetSymbolAddress((void**)&ea,  g_ea);
    cudaGetSymbolAddress((void**)&Wqb, g_Wqb);
    cudaGetSymbolAddress((void**)&Wkb, g_Wkb);
    cudaGetSymbolAddress((void**)&eh,  g_eh);
    cudaGetSymbolAddress((void**)&Wvh, g_Wvh);
    cudaGetSymbolAddress((void**)&Qa,  g_Qa);
    cudaGetSymbolAddress((void**)&Kb,  g_Kb);
    cudaGetSymbolAddress((void**)&Ph,  g_Ph);
    cudaGetSymbolAddress((void**)&Vth, g_Vth);

    const int smem128 = 3 * (128 + 128) * 128;   // 96 KB
    const int smem64  = 3 * (128 + 64) * 128;    // 72 KB
    cudaFuncSetAttribute((const void*)gemm_nt<128, false, 2>, cudaFuncAttributeMaxDynamicSharedMemorySize, smem128);
    cudaFuncSetAttribute((const void*)gemm_nt<128, true, 2>,  cudaFuncAttributeMaxDynamicSharedMemorySize, smem128);
    cudaFuncSetAttribute((const void*)gemm_nt<64, true, 3>,   cudaFuncAttributeMaxDynamicSharedMemorySize, smem64);

    dim3 blk(128);
    dim3 blk256(256);

    // 1. merged input conversions
    convert_all<<<(E4 + 3 * W4) / 256, blk256>>>(embs, Wq, Wk, Wv, ea, eh, Wqb, Wkb, Wvh);

    // 2. fused Q+K projection (bf16 3-term in, fp16 2-seg out)
    gemm_nt<128, false, 2><<<dim3(2 * HID / 128, NSEQ / BM), blk, smem128>>>(
        (const u16*)ea, (const u16*)Wqb, (const u16*)Wkb,
        bq, bk, nullptr, nullptr,
        nullptr, nullptr, Qa, Kb,
        HID, 0, 1, HID, HID, 3 * DIN);

    // 3. Vt projection (fp16 1-term), 3 CTAs/SM
    gemm_nt<64, true, 3><<<dim3(NSEQ / 64, HID / BM), blk, smem64>>>(
        Wvh, eh, nullptr,
        nullptr, nullptr, bv, nullptr,
        nullptr, Vth, nullptr, nullptr,
        0, 0, 0, 0, NSEQ, DIN);

    // 4. S = Q @ K^T (fp16 2-term), BN=128, 2 CTAs/SM (round-9 best shape)
    gemm_nt<128, true, 2><<<dim3(NSEQ / 128, NSEQ / BM), blk, smem128>>>(
        Qa, Kb, nullptr,
        nullptr, nullptr, nullptr, nullptr,
        S, nullptr, nullptr, nullptr,
        0, 0, 0, 0, NSEQ, 2 * HID);

    // 5. softmax -> fp16 exp + rowInv
    softmax_half<<<NSEQ, blk256>>>(S, Ph, rowInv);

    // 6. out = (P @ Vt^T) * rowInv (fp16 1-term), 3 CTAs/SM
    gemm_nt<64, true, 3><<<dim3(HID / 64, NSEQ / BM), blk, smem64>>>(
        Ph, Vth, nullptr,
        nullptr, nullptr, nullptr, rowInv,
        out, nullptr, nullptr, nullptr,
        0, 0, 0, 0, HID, NSEQ);
}